// round 1
// baseline (speedup 1.0000x reference)
#include <cuda_runtime.h>
#include <math.h>

#define BB 32
#define CC 256
#define DD 1024
#define QQ 128

// q_output starts after d_output in the flat output buffer
#define QOFF ((size_t)BB * 4 * CC * DD)   // 33,554,432 floats

// ---------------- scratch (device globals; no allocation allowed) -----------
__device__ float g_sim [BB * QQ * DD];   // raw sim[b][q][d]            16 MB
__device__ float g_s1  [BB * QQ * DD];   // softmax over q (axis -2)    16 MB
__device__ float g_s2  [BB * QQ * DD];   // softmax over d (axis -1)    16 MB
__device__ float g_dd2q[BB * CC * DD];   // d_d2q[b][c][d]              32 MB
__device__ float g_qq2d[BB * CC * QQ];   // q_q2d[b][c][q]               4 MB

// ============================================================================
// Kernel 1: sim[b,q,d] = sum_c (w_s[c]*query[b,c,q])*doc[b,c,d]
//                        + a_q[b,q] + a_d[b,d]
// then s1 = softmax over q (rows), fused (M-tile = 128 = all of q).
// Writes g_sim (raw, for s2) and g_s1.
// Grid: (D/128, B), block 256. Tile 128x128, Kt=16, 8x8 per thread.
// ============================================================================
__global__ void __launch_bounds__(256) k_sim(const float* __restrict__ doc,
                                             const float* __restrict__ query,
                                             const float* __restrict__ W) {
    const int b  = blockIdx.y;
    const int d0 = blockIdx.x * 128;
    const float* docb = doc   + (size_t)b * CC * DD;
    const float* qb   = query + (size_t)b * CC * QQ;

    __shared__ float sA[16][128];     // (w_s*query)[k][q]
    __shared__ float sB[16][128];     // doc[k][d]
    __shared__ float red[16][128];    // cross-thread softmax partials
    __shared__ float colv[128];       // per-column broadcast (max, then 1/sum)
    __shared__ float biasq[128];
    __shared__ float biasd[128];

    const int tid = threadIdx.x;
    const int ty  = tid >> 4;         // 0..15 -> q rows ty*8..ty*8+7
    const int tx  = tid & 15;         // 0..15 -> d cols tx*8..tx*8+7

    // ---- prologue: a_q[q] and a_d[d] for this tile (coalesced over threads)
    if (tid < 128) {
        float aq = 0.f, ad = 0.f;
        #pragma unroll 4
        for (int c = 0; c < CC; ++c) {
            aq = fmaf(W[CC + c], qb[c * QQ + tid], aq);
            ad = fmaf(W[c],      docb[(size_t)c * DD + d0 + tid], ad);
        }
        biasq[tid] = aq;
        biasd[tid] = ad;
    }

    float acc[8][8] = {};

    const int lk = tid >> 4;          // 0..15 (k row to load)
    const int lc = (tid & 15) * 8;    // 0..120 (8 contiguous cols)

    for (int k0 = 0; k0 < CC; k0 += 16) {
        __syncthreads();
        const float ws = W[2 * CC + k0 + lk];
        float4 a0 = *(const float4*)(qb + (size_t)(k0 + lk) * QQ + lc);
        float4 a1 = *(const float4*)(qb + (size_t)(k0 + lk) * QQ + lc + 4);
        float4 b0 = *(const float4*)(docb + (size_t)(k0 + lk) * DD + d0 + lc);
        float4 b1 = *(const float4*)(docb + (size_t)(k0 + lk) * DD + d0 + lc + 4);
        sA[lk][lc + 0] = ws * a0.x; sA[lk][lc + 1] = ws * a0.y;
        sA[lk][lc + 2] = ws * a0.z; sA[lk][lc + 3] = ws * a0.w;
        sA[lk][lc + 4] = ws * a1.x; sA[lk][lc + 5] = ws * a1.y;
        sA[lk][lc + 6] = ws * a1.z; sA[lk][lc + 7] = ws * a1.w;
        *(float4*)&sB[lk][lc]     = b0;
        *(float4*)&sB[lk][lc + 4] = b1;
        __syncthreads();
        #pragma unroll
        for (int kk = 0; kk < 16; ++kk) {
            float a[8], bv[8];
            *(float4*)(a)      = *(const float4*)(&sA[kk][ty * 8]);
            *(float4*)(a + 4)  = *(const float4*)(&sA[kk][ty * 8 + 4]);
            *(float4*)(bv)     = *(const float4*)(&sB[kk][tx * 8]);
            *(float4*)(bv + 4) = *(const float4*)(&sB[kk][tx * 8 + 4]);
            #pragma unroll
            for (int i = 0; i < 8; ++i)
                #pragma unroll
                for (int j = 0; j < 8; ++j)
                    acc[i][j] = fmaf(a[i], bv[j], acc[i][j]);
        }
    }
    __syncthreads();

    // ---- bias add + write raw sim (needed for s2)
    float* simb = g_sim + ((size_t)b * QQ + ty * 8) * DD + d0 + tx * 8;
    #pragma unroll
    for (int i = 0; i < 8; ++i) {
        #pragma unroll
        for (int j = 0; j < 8; ++j)
            acc[i][j] += biasq[ty * 8 + i] + biasd[tx * 8 + j];
        *(float4*)(simb + (size_t)i * DD) =
            make_float4(acc[i][0], acc[i][1], acc[i][2], acc[i][3]);
        *(float4*)(simb + (size_t)i * DD + 4) =
            make_float4(acc[i][4], acc[i][5], acc[i][6], acc[i][7]);
    }

    // ---- column softmax over q (rows) -> s1
    #pragma unroll
    for (int j = 0; j < 8; ++j) {
        float m = acc[0][j];
        #pragma unroll
        for (int i = 1; i < 8; ++i) m = fmaxf(m, acc[i][j]);
        red[ty][tx * 8 + j] = m;
    }
    __syncthreads();
    if (tid < 128) {
        float m = red[0][tid];
        #pragma unroll
        for (int t = 1; t < 16; ++t) m = fmaxf(m, red[t][tid]);
        colv[tid] = m;
    }
    __syncthreads();
    #pragma unroll
    for (int j = 0; j < 8; ++j) {
        const float m = colv[tx * 8 + j];
        float s = 0.f;
        #pragma unroll
        for (int i = 0; i < 8; ++i) {
            acc[i][j] = __expf(acc[i][j] - m);
            s += acc[i][j];
        }
        red[ty][tx * 8 + j] = s;
    }
    __syncthreads();
    if (tid < 128) {
        float s = 0.f;
        #pragma unroll
        for (int t = 0; t < 16; ++t) s += red[t][tid];
        colv[tid] = 1.f / s;
    }
    __syncthreads();
    float* s1b = g_s1 + ((size_t)b * QQ + ty * 8) * DD + d0 + tx * 8;
    #pragma unroll
    for (int i = 0; i < 8; ++i) {
        #pragma unroll
        for (int j = 0; j < 8; ++j) acc[i][j] *= colv[tx * 8 + j];
        *(float4*)(s1b + (size_t)i * DD) =
            make_float4(acc[i][0], acc[i][1], acc[i][2], acc[i][3]);
        *(float4*)(s1b + (size_t)i * DD + 4) =
            make_float4(acc[i][4], acc[i][5], acc[i][6], acc[i][7]);
    }
}

// ============================================================================
// Kernel 2: s2 = softmax of g_sim over d (1024 contiguous elems per row).
// Grid: B*Q blocks, 256 threads, float4 per thread.
// ============================================================================
__global__ void __launch_bounds__(256) k_s2k() {
    const size_t row = blockIdx.x;
    const float4* src = (const float4*)(g_sim + row * DD);
    float4* dst       = (float4*)(g_s2 + row * DD);
    const int tid = threadIdx.x;
    __shared__ float sred[8];
    __shared__ float sbc;

    float4 v = src[tid];
    float m = fmaxf(fmaxf(v.x, v.y), fmaxf(v.z, v.w));
    #pragma unroll
    for (int o = 16; o > 0; o >>= 1) m = fmaxf(m, __shfl_xor_sync(0xffffffffu, m, o));
    if ((tid & 31) == 0) sred[tid >> 5] = m;
    __syncthreads();
    if (tid == 0) {
        float t = sred[0];
        #pragma unroll
        for (int i = 1; i < 8; ++i) t = fmaxf(t, sred[i]);
        sbc = t;
    }
    __syncthreads();
    const float M = sbc;
    float4 e;
    e.x = __expf(v.x - M); e.y = __expf(v.y - M);
    e.z = __expf(v.z - M); e.w = __expf(v.w - M);
    float s = e.x + e.y + e.z + e.w;
    #pragma unroll
    for (int o = 16; o > 0; o >>= 1) s += __shfl_xor_sync(0xffffffffu, s, o);
    __syncthreads();                       // protect sred reuse
    if ((tid & 31) == 0) sred[tid >> 5] = s;
    __syncthreads();
    if (tid == 0) {
        float t = 0.f;
        #pragma unroll
        for (int i = 0; i < 8; ++i) t += sred[i];
        sbc = 1.f / t;
    }
    __syncthreads();
    const float r = sbc;
    dst[tid] = make_float4(e.x * r, e.y * r, e.z * r, e.w * r);
}

// ============================================================================
// Kernel 3 (NN): out[c,d] = sum_q A[c,q] * s1[q,d]
//   mode 0: A = query  -> d_d2q. Writes d_out ch [0,C)=doc copy, [C,2C)=d_d2q,
//           [2C,3C)=doc*d_d2q, and g_dd2q.
//   mode 1: A = g_qq2d -> d_q2d. Writes d_out ch [3C,4C)=doc*d_q2d.
// M=256, N=1024, K=128. Tile 128x128x16. Grid (8, 2, B).
// ============================================================================
__global__ void __launch_bounds__(256) k_gemm_nn(const float* __restrict__ query,
                                                 const float* __restrict__ doc,
                                                 float* __restrict__ out,
                                                 int mode) {
    const int b  = blockIdx.z;
    const int m0 = blockIdx.y * 128;
    const int n0 = blockIdx.x * 128;
    const float* A    = (mode == 0) ? (query + (size_t)b * CC * QQ)
                                    : (g_qq2d + (size_t)b * CC * QQ);
    const float* Bm   = g_s1 + (size_t)b * QQ * DD;
    const float* docb = doc + (size_t)b * CC * DD;

    __shared__ float sA[16][136];   // transposed A tile [k][m], padded
    __shared__ float sB[16][128];   // s1 tile [k][n]

    const int tid = threadIdx.x;
    const int ty = tid >> 4, tx = tid & 15;
    float acc[8][8] = {};

    const int ar = tid >> 1, akc = (tid & 1) * 8;   // A: 128 rows x 16 k
    const int bk = tid >> 4, bc = (tid & 15) * 8;   // B: 16 rows x 128 n

    for (int k0 = 0; k0 < QQ; k0 += 16) {
        __syncthreads();
        float4 a0 = *(const float4*)(A + (size_t)(m0 + ar) * QQ + k0 + akc);
        float4 a1 = *(const float4*)(A + (size_t)(m0 + ar) * QQ + k0 + akc + 4);
        sA[akc + 0][ar] = a0.x; sA[akc + 1][ar] = a0.y;
        sA[akc + 2][ar] = a0.z; sA[akc + 3][ar] = a0.w;
        sA[akc + 4][ar] = a1.x; sA[akc + 5][ar] = a1.y;
        sA[akc + 6][ar] = a1.z; sA[akc + 7][ar] = a1.w;
        *(float4*)&sB[bk][bc]     = *(const float4*)(Bm + (size_t)(k0 + bk) * DD + n0 + bc);
        *(float4*)&sB[bk][bc + 4] = *(const float4*)(Bm + (size_t)(k0 + bk) * DD + n0 + bc + 4);
        __syncthreads();
        #pragma unroll
        for (int kk = 0; kk < 16; ++kk) {
            float a[8], bv[8];
            *(float4*)(a)      = *(const float4*)(&sA[kk][ty * 8]);
            *(float4*)(a + 4)  = *(const float4*)(&sA[kk][ty * 8 + 4]);
            *(float4*)(bv)     = *(const float4*)(&sB[kk][tx * 8]);
            *(float4*)(bv + 4) = *(const float4*)(&sB[kk][tx * 8 + 4]);
            #pragma unroll
            for (int i = 0; i < 8; ++i)
                #pragma unroll
                for (int j = 0; j < 8; ++j)
                    acc[i][j] = fmaf(a[i], bv[j], acc[i][j]);
        }
    }

    const size_t dbase = (size_t)b * 4 * CC * DD;
    #pragma unroll
    for (int i = 0; i < 8; ++i) {
        const int m = m0 + ty * 8 + i;
        const size_t roff = (size_t)m * DD + n0 + tx * 8;
        float4 dv0 = *(const float4*)(docb + roff);
        float4 dv1 = *(const float4*)(docb + roff + 4);
        float4 v0 = make_float4(acc[i][0], acc[i][1], acc[i][2], acc[i][3]);
        float4 v1 = make_float4(acc[i][4], acc[i][5], acc[i][6], acc[i][7]);
        float4 p0 = make_float4(dv0.x * v0.x, dv0.y * v0.y, dv0.z * v0.z, dv0.w * v0.w);
        float4 p1 = make_float4(dv1.x * v1.x, dv1.y * v1.y, dv1.z * v1.z, dv1.w * v1.w);
        if (mode == 0) {
            *(float4*)(out + dbase + roff)     = dv0;                 // doc copy
            *(float4*)(out + dbase + roff + 4) = dv1;
            *(float4*)(out + dbase + (size_t)CC * DD + roff)     = v0; // d_d2q
            *(float4*)(out + dbase + (size_t)CC * DD + roff + 4) = v1;
            *(float4*)(out + dbase + (size_t)2 * CC * DD + roff)     = p0; // doc*d_d2q
            *(float4*)(out + dbase + (size_t)2 * CC * DD + roff + 4) = p1;
            *(float4*)(g_dd2q + (size_t)b * CC * DD + roff)     = v0;
            *(float4*)(g_dd2q + (size_t)b * CC * DD + roff + 4) = v1;
        } else {
            *(float4*)(out + dbase + (size_t)3 * CC * DD + roff)     = p0; // doc*d_q2d
            *(float4*)(out + dbase + (size_t)3 * CC * DD + roff + 4) = p1;
        }
    }
}

// ============================================================================
// Kernel 4 (NT): out[c,q] = sum_d A[c,d] * s2[q,d]
//   mode 0: A = doc    -> q_q2d. Writes q_out ch [0,C)=query copy, [C,2C)=q_q2d,
//           [2C,3C)=query*q_q2d, and g_qq2d.
//   mode 1: A = g_dd2q -> q_d2q. Writes q_out ch [3C,4C)=query*q_d2q.
// M=256 (Mt=64), N=128 (full), K=1024 (Kt=16). Grid (4, B).
// ============================================================================
__global__ void __launch_bounds__(256) k_gemm_nt(const float* __restrict__ doc,
                                                 const float* __restrict__ query,
                                                 float* __restrict__ out,
                                                 int mode) {
    const int b  = blockIdx.y;
    const int m0 = blockIdx.x * 64;
    const float* A   = (mode == 0) ? (doc + (size_t)b * CC * DD)
                                   : (g_dd2q + (size_t)b * CC * DD);
    const float* Bm  = g_s2 + (size_t)b * QQ * DD;
    const float* qrb = query + (size_t)b * CC * QQ;

    __shared__ float sA[16][72];    // [k][m], m<64
    __shared__ float sB[16][136];   // [k][n], n<128

    const int tid = threadIdx.x;
    const int ty = tid >> 4, tx = tid & 15;
    float acc[4][8] = {};

    const int ar = tid & 63,  akc = (tid >> 6) * 4;   // A: 64 rows, 4 k each
    const int br = tid & 127, bkc = (tid >> 7) * 8;   // B: 128 rows, 8 k each

    for (int k0 = 0; k0 < DD; k0 += 16) {
        __syncthreads();
        float4 a0 = *(const float4*)(A + (size_t)(m0 + ar) * DD + k0 + akc);
        float4 b0 = *(const float4*)(Bm + (size_t)br * DD + k0 + bkc);
        float4 b1 = *(const float4*)(Bm + (size_t)br * DD + k0 + bkc + 4);
        sA[akc + 0][ar] = a0.x; sA[akc + 1][ar] = a0.y;
        sA[akc + 2][ar] = a0.z; sA[akc + 3][ar] = a0.w;
        sB[bkc + 0][br] = b0.x; sB[bkc + 1][br] = b0.y;
        sB[bkc + 2][br] = b0.z; sB[bkc + 3][br] = b0.w;
        sB[bkc + 4][br] = b1.x; sB[bkc + 5][br] = b1.y;
        sB[bkc + 6][br] = b1.z; sB[bkc + 7][br] = b1.w;
        __syncthreads();
        #pragma unroll
        for (int kk = 0; kk < 16; ++kk) {
            float a[4], bv[8];
            *(float4*)(a)      = *(const float4*)(&sA[kk][ty * 4]);
            *(float4*)(bv)     = *(const float4*)(&sB[kk][tx * 8]);
            *(float4*)(bv + 4) = *(const float4*)(&sB[kk][tx * 8 + 4]);
            #pragma unroll
            for (int i = 0; i < 4; ++i)
                #pragma unroll
                for (int j = 0; j < 8; ++j)
                    acc[i][j] = fmaf(a[i], bv[j], acc[i][j]);
        }
    }

    const size_t qbase = QOFF + (size_t)b * 4 * CC * QQ;
    #pragma unroll
    for (int i = 0; i < 4; ++i) {
        const int m = m0 + ty * 4 + i;
        const size_t roff = (size_t)m * QQ + tx * 8;
        float4 q0 = *(const float4*)(qrb + roff);
        float4 q1 = *(const float4*)(qrb + roff + 4);
        float4 v0 = make_float4(acc[i][0], acc[i][1], acc[i][2], acc[i][3]);
        float4 v1 = make_float4(acc[i][4], acc[i][5], acc[i][6], acc[i][7]);
        float4 p0 = make_float4(q0.x * v0.x, q0.y * v0.y, q0.z * v0.z, q0.w * v0.w);
        float4 p1 = make_float4(q1.x * v1.x, q1.y * v1.y, q1.z * v1.z, q1.w * v1.w);
        if (mode == 0) {
            *(float4*)(out + qbase + roff)     = q0;                  // query copy
            *(float4*)(out + qbase + roff + 4) = q1;
            *(float4*)(out + qbase + (size_t)CC * QQ + roff)     = v0; // q_q2d
            *(float4*)(out + qbase + (size_t)CC * QQ + roff + 4) = v1;
            *(float4*)(out + qbase + (size_t)2 * CC * QQ + roff)     = p0; // query*q_q2d
            *(float4*)(out + qbase + (size_t)2 * CC * QQ + roff + 4) = p1;
            *(float4*)(g_qq2d + (size_t)b * CC * QQ + roff)     = v0;
            *(float4*)(g_qq2d + (size_t)b * CC * QQ + roff + 4) = v1;
        } else {
            *(float4*)(out + qbase + (size_t)3 * CC * QQ + roff)     = p0; // query*q_d2q
            *(float4*)(out + qbase + (size_t)3 * CC * QQ + roff + 4) = p1;
        }
    }
}

// ============================================================================
extern "C" void kernel_launch(void* const* d_in, const int* in_sizes, int n_in,
                              void* d_out, int out_size) {
    const float* doc = nullptr;
    const float* query = nullptr;
    const float* W = nullptr;
    for (int i = 0; i < n_in; ++i) {
        if      (in_sizes[i] == BB * CC * DD) doc   = (const float*)d_in[i];
        else if (in_sizes[i] == BB * CC * QQ) query = (const float*)d_in[i];
        else if (in_sizes[i] == 3 * CC)       W     = (const float*)d_in[i];
    }
    float* out = (float*)d_out;

    k_sim    <<<dim3(DD / 128, BB), 256>>>(doc, query, W);
    k_s2k    <<<BB * QQ, 256>>>();
    k_gemm_nn<<<dim3(DD / 128, CC / 128, BB), 256>>>(query, doc, out, 0); // d_d2q
    k_gemm_nt<<<dim3(CC / 64, BB), 256>>>(doc, query, out, 0);            // q_q2d
    k_gemm_nn<<<dim3(DD / 128, CC / 128, BB), 256>>>(query, doc, out, 1); // d_q2d
    k_gemm_nt<<<dim3(CC / 64, BB), 256>>>(doc, query, out, 1);            // q_d2q
}

// round 4
// speedup vs baseline: 1.2089x; 1.2089x over previous
#include <cuda_runtime.h>
#include <cstdint>
#include <math.h>

#define BB 32
#define CC 256
#define DD 1024
#define QQ 128

#define QOFF ((size_t)BB * 4 * CC * DD)   // q_output offset in floats
#define STG 132                            // stage stride (floats)
#define TST 36                             // mma tile stride (floats)

// ---------------- scratch (device globals) ----------------------------------
__device__ float g_sim [BB * QQ * DD];   // sim with biases          16 MB
__device__ float g_s1t [BB * DD * QQ];   // softmax over q, transposed [d][q]
__device__ float g_s2  [BB * QQ * DD];   // softmax over d           16 MB
__device__ float g_dd2q[BB * CC * DD];   // d_d2q                    32 MB
__device__ float g_qq2d[BB * CC * QQ];   // q_q2d                     4 MB
__device__ float g_qT  [BB * QQ * CC];   // query^T [q][c]            4 MB
__device__ float g_dT  [BB * DD * CC];   // (w_s*doc)^T [d][c]       32 MB
__device__ float g_aq  [BB * QQ];
__device__ float g_ad  [BB * DD];

// ---------------- helpers ----------------------------------------------------
__device__ __forceinline__ uint32_t cvt_tf32(float f) {
    uint32_t r;
    asm("cvt.rna.tf32.f32 %0, %1;" : "=r"(r) : "f"(f));
    return r;
}

__device__ __forceinline__ void mma_tf32(float c[4], const uint32_t a[4],
                                         const uint32_t b[2]) {
    asm volatile(
        "mma.sync.aligned.m16n8k8.row.col.f32.tf32.tf32.f32 "
        "{%0,%1,%2,%3}, {%4,%5,%6,%7}, {%8,%9}, {%0,%1,%2,%3};\n"
        : "+f"(c[0]), "+f"(c[1]), "+f"(c[2]), "+f"(c[3])
        : "r"(a[0]), "r"(a[1]), "r"(a[2]), "r"(a[3]), "r"(b[0]), "r"(b[1]));
}

// Load ROWS x 32 fp32 tile (K-major, leading dim ldk) -> smem stride-36, tf32.
template<int ROWS>
__device__ __forceinline__ void load_tile(float* dst, const float* src,
                                          int ldk, int k0, int tid) {
    #pragma unroll
    for (int i = 0; i < ROWS / 32; ++i) {
        int idx = i * 256 + tid;
        int row = idx >> 3, cb = (idx & 7) * 4;
        float4 v = *(const float4*)(src + (size_t)row * ldk + k0 + cb);
        uint4 u;
        u.x = cvt_tf32(v.x); u.y = cvt_tf32(v.y);
        u.z = cvt_tf32(v.z); u.w = cvt_tf32(v.w);
        *(uint4*)(dst + row * TST + cb) = u;
    }
}

// GEMM core: C[MTILE x NTILE] = A[MTILE x K] * B[128 x K]^T, both K-major.
// MTILE=128 -> warps 4x2 (NJ=8, NTILE=128); MTILE=64 -> warps 2x4 (NJ=4, NTILE=128).
template<int MTILE>
__device__ __forceinline__ void run_gemm(const float* A, int lda,
                                         const float* Bm, int ldb, int kIters,
                                         float* sA, float* sB,
                                         float (*c)[4], int tid) {
    const int wid = tid >> 5, lane = tid & 31;
    const int NJ = (MTILE == 128) ? 8 : 4;
    const int wm = (MTILE == 128) ? (wid & 3) * 32 : (wid & 1) * 32;
    const int wn = (MTILE == 128) ? (wid >> 2) * 64 : (wid >> 1) * 32;
    const int g = lane >> 2, tg = lane & 3;

    for (int it = 0; it < kIters; ++it) {
        __syncthreads();
        load_tile<MTILE>(sA, A, lda, it * 32, tid);
        load_tile<128>(sB, Bm, ldb, it * 32, tid);
        __syncthreads();
        #pragma unroll
        for (int ks = 0; ks < 4; ++ks) {
            const int kb = ks * 8;
            uint32_t a[2][4], b[8][2];
            #pragma unroll
            for (int i = 0; i < 2; ++i) {
                const float* p = sA + (wm + i * 16 + g) * TST + kb + tg;
                a[i][0] = __float_as_uint(p[0]);
                a[i][1] = __float_as_uint(p[8 * TST]);
                a[i][2] = __float_as_uint(p[4]);
                a[i][3] = __float_as_uint(p[8 * TST + 4]);
            }
            #pragma unroll
            for (int j = 0; j < NJ; ++j) {
                const float* p = sB + (wn + j * 8 + g) * TST + kb + tg;
                b[j][0] = __float_as_uint(p[0]);
                b[j][1] = __float_as_uint(p[4]);
            }
            #pragma unroll
            for (int i = 0; i < 2; ++i)
                #pragma unroll
                for (int j = 0; j < NJ; ++j)
                    mma_tf32(c[i * 8 + j], a[i], b[j]);
        }
    }
}

// Fragments -> stage smem (stride STG), optional row/col bias.
template<int MTILE>
__device__ __forceinline__ void frags_to_stage(float* stage, float (*c)[4],
                                               int tid, const float* br,
                                               const float* bc) {
    const int wid = tid >> 5, lane = tid & 31;
    const int NJ = (MTILE == 128) ? 8 : 4;
    const int wm = (MTILE == 128) ? (wid & 3) * 32 : (wid & 1) * 32;
    const int wn = (MTILE == 128) ? (wid >> 2) * 64 : (wid >> 1) * 32;
    const int g = lane >> 2, tg = lane & 3;
    __syncthreads();                 // tiles fully consumed (stage aliases them)
    #pragma unroll
    for (int i = 0; i < 2; ++i) {
        const int r0 = wm + i * 16 + g, r1 = r0 + 8;
        const float a0 = br ? br[r0] : 0.f, a1 = br ? br[r1] : 0.f;
        #pragma unroll
        for (int j = 0; j < NJ; ++j) {
            const int col = wn + j * 8 + 2 * tg;
            const float b0 = bc ? bc[col] : 0.f, b1 = bc ? bc[col + 1] : 0.f;
            float* f = c[i * 8 + j];
            stage[r0 * STG + col]     = f[0] + a0 + b0;
            stage[r0 * STG + col + 1] = f[1] + a0 + b1;
            stage[r1 * STG + col]     = f[2] + a1 + b0;
            stage[r1 * STG + col + 1] = f[3] + a1 + b1;
        }
    }
    __syncthreads();
}

// ============================================================================
// Transposes + bias GEMVs
// ============================================================================
__global__ void k_t_q(const float* __restrict__ query) {
    __shared__ float tile[32][33];
    const int b = blockIdx.z, q0 = blockIdx.x * 32, c0 = blockIdx.y * 32;
    const int tx = threadIdx.x, ty = threadIdx.y;
    const float* src = query + (size_t)b * CC * QQ;
    float* dst = g_qT + (size_t)b * QQ * CC;
    #pragma unroll
    for (int r = ty; r < 32; r += 8)
        tile[r][tx] = src[(size_t)(c0 + r) * QQ + q0 + tx];
    __syncthreads();
    #pragma unroll
    for (int r = ty; r < 32; r += 8)
        dst[(size_t)(q0 + r) * CC + c0 + tx] = tile[tx][r];
}
__global__ void k_t_d(const float* __restrict__ doc, const float* __restrict__ W) {
    __shared__ float tile[32][33];
    const int b = blockIdx.z, d0 = blockIdx.x * 32, c0 = blockIdx.y * 32;
    const int tx = threadIdx.x, ty = threadIdx.y;
    const float* src = doc + (size_t)b * CC * DD;
    float* dst = g_dT + (size_t)b * DD * CC;
    #pragma unroll
    for (int r = ty; r < 32; r += 8)
        tile[r][tx] = src[(size_t)(c0 + r) * DD + d0 + tx];
    __syncthreads();
    const float ws = W[2 * CC + c0 + tx];
    #pragma unroll
    for (int r = ty; r < 32; r += 8)
        dst[(size_t)(d0 + r) * CC + c0 + tx] = tile[tx][r] * ws;
}
__global__ void __launch_bounds__(256) k_bias(const float* __restrict__ doc,
                                              const float* __restrict__ query,
                                              const float* __restrict__ W) {
    const int b = blockIdx.x, tid = threadIdx.x;
    const float* qb = query + (size_t)b * CC * QQ;
    const float* db = doc + (size_t)b * CC * DD;
    if (tid < QQ) {
        float s = 0.f;
        #pragma unroll 4
        for (int c = 0; c < CC; ++c) s = fmaf(W[CC + c], qb[c * QQ + tid], s);
        g_aq[b * QQ + tid] = s;
    }
    for (int d = tid; d < DD; d += 256) {
        float s = 0.f;
        #pragma unroll 4
        for (int c = 0; c < CC; ++c) s = fmaf(W[c], db[(size_t)c * DD + d], s);
        g_ad[b * DD + d] = s;
    }
}

// ============================================================================
// sim: sim[q,d] = qT[q,:].dT[d,:] + aq + ad  (K=256), write g_sim,
// column softmax over q -> g_s1t[d][q]. Grid (8, B), 256 thr.
// ============================================================================
__global__ void __launch_bounds__(256) k_mma_sim() {
    extern __shared__ float sm[];
    __shared__ float sh_aq[128];
    __shared__ float sh_ad[128];
    const int b = blockIdx.y, n0 = blockIdx.x * 128;
    const int tid = threadIdx.x, wid = tid >> 5, lid = tid & 31;
    if (tid < 128) {
        sh_aq[tid] = g_aq[b * QQ + tid];
        sh_ad[tid] = g_ad[b * DD + n0 + tid];
    }
    float c[16][4] = {};
    float* sA = sm;
    float* sB = sm + 128 * TST;
    float* stage = sm;
    const float* A  = g_qT + (size_t)b * QQ * CC;
    const float* Bm = g_dT + (size_t)b * DD * CC + (size_t)n0 * CC;
    run_gemm<128>(A, CC, Bm, CC, CC / 32, sA, sB, c, tid);
    frags_to_stage<128>(stage, c, tid, sh_aq, sh_ad);

    float* simb = g_sim + (size_t)b * QQ * DD;
    for (int r = wid; r < 128; r += 8)
        *(float4*)(simb + (size_t)r * DD + n0 + lid * 4) =
            *(float4*)&stage[r * STG + lid * 4];
    __syncthreads();

    if (tid < 128) {
        float m = -1e30f;
        #pragma unroll 4
        for (int q = 0; q < 128; ++q) m = fmaxf(m, stage[q * STG + tid]);
        float s = 0.f;
        #pragma unroll 4
        for (int q = 0; q < 128; ++q) {
            float e = __expf(stage[q * STG + tid] - m);
            stage[q * STG + tid] = e;
            s += e;
        }
        const float inv = 1.f / s;
        float* dst = g_s1t + ((size_t)b * DD + n0 + tid) * QQ;
        #pragma unroll 4
        for (int q = 0; q < 128; q += 4)
            *(float4*)(dst + q) = make_float4(stage[(q + 0) * STG + tid] * inv,
                                              stage[(q + 1) * STG + tid] * inv,
                                              stage[(q + 2) * STG + tid] * inv,
                                              stage[(q + 3) * STG + tid] * inv);
    }
}

// ============================================================================
// s2: row softmax of g_sim over d. Grid B*Q, 256 threads.
// ============================================================================
__global__ void __launch_bounds__(256) k_s2k() {
    const size_t row = blockIdx.x;
    const float4* src = (const float4*)(g_sim + row * DD);
    float4* dst = (float4*)(g_s2 + row * DD);
    const int tid = threadIdx.x;
    __shared__ float sred[8];
    __shared__ float sbc;
    float4 v = src[tid];
    float m = fmaxf(fmaxf(v.x, v.y), fmaxf(v.z, v.w));
    #pragma unroll
    for (int o = 16; o > 0; o >>= 1) m = fmaxf(m, __shfl_xor_sync(0xffffffffu, m, o));
    if ((tid & 31) == 0) sred[tid >> 5] = m;
    __syncthreads();
    if (tid == 0) {
        float t = sred[0];
        #pragma unroll
        for (int i = 1; i < 8; ++i) t = fmaxf(t, sred[i]);
        sbc = t;
    }
    __syncthreads();
    const float M = sbc;
    float4 e;
    e.x = __expf(v.x - M); e.y = __expf(v.y - M);
    e.z = __expf(v.z - M); e.w = __expf(v.w - M);
    float s = e.x + e.y + e.z + e.w;
    #pragma unroll
    for (int o = 16; o > 0; o >>= 1) s += __shfl_xor_sync(0xffffffffu, s, o);
    __syncthreads();
    if ((tid & 31) == 0) sred[tid >> 5] = s;
    __syncthreads();
    if (tid == 0) {
        float t = 0.f;
        #pragma unroll
        for (int i = 0; i < 8; ++i) t += sred[i];
        sbc = 1.f / t;
    }
    __syncthreads();
    const float r = sbc;
    dst[tid] = make_float4(e.x * r, e.y * r, e.z * r, e.w * r);
}

// ============================================================================
// NN: out[c,d] = A[c,:q] . s1t[d,:q]  (K=128). Grid (8, 2, B).
//   mode 0: A=query  -> ch0 doc, ch1 d_d2q, ch2 doc*d_d2q, + g_dd2q
//   mode 1: A=g_qq2d -> ch3 doc*d_q2d
// ============================================================================
__global__ void __launch_bounds__(256) k_mma_nn(const float* __restrict__ query,
                                                const float* __restrict__ doc,
                                                float* __restrict__ out, int mode) {
    extern __shared__ float sm[];
    const int b = blockIdx.z, m0 = blockIdx.y * 128, n0 = blockIdx.x * 128;
    const int tid = threadIdx.x, wid = tid >> 5, lid = tid & 31;
    float c[16][4] = {};
    float* sA = sm;
    float* sB = sm + 128 * TST;
    float* stage = sm;
    const float* A = (mode == 0 ? query + (size_t)b * CC * QQ
                                : g_qq2d + (size_t)b * CC * QQ) + (size_t)m0 * QQ;
    const float* Bm = g_s1t + (size_t)b * DD * QQ + (size_t)n0 * QQ;
    run_gemm<128>(A, QQ, Bm, QQ, QQ / 32, sA, sB, c, tid);
    frags_to_stage<128>(stage, c, tid, nullptr, nullptr);

    const float* docb = doc + (size_t)b * CC * DD;
    const size_t dbase = (size_t)b * 4 * CC * DD;
    for (int r = wid; r < 128; r += 8) {
        const size_t roff = (size_t)(m0 + r) * DD + n0 + lid * 4;
        float4 v = *(float4*)&stage[r * STG + lid * 4];
        float4 dv = *(const float4*)(docb + roff);
        float4 p = make_float4(dv.x * v.x, dv.y * v.y, dv.z * v.z, dv.w * v.w);
        if (mode == 0) {
            *(float4*)(out + dbase + roff) = dv;
            *(float4*)(out + dbase + (size_t)CC * DD + roff) = v;
            *(float4*)(out + dbase + (size_t)2 * CC * DD + roff) = p;
            *(float4*)(g_dd2q + (size_t)b * CC * DD + roff) = v;
        } else {
            *(float4*)(out + dbase + (size_t)3 * CC * DD + roff) = p;
        }
    }
}

// ============================================================================
// NT: out[c,q] = A[c,:d] . s2[q,:d]  (K=1024). MTILE=64, grid (4, B).
//   mode 0: A=doc    -> ch0 query, ch1 q_q2d, ch2 query*q_q2d, + g_qq2d
//   mode 1: A=g_dd2q -> ch3 query*q_d2q
// ============================================================================
__global__ void __launch_bounds__(256) k_mma_nt(const float* __restrict__ doc,
                                                const float* __restrict__ query,
                                                float* __restrict__ out, int mode) {
    extern __shared__ float sm[];
    const int b = blockIdx.y, m0 = blockIdx.x * 64;
    const int tid = threadIdx.x, wid = tid >> 5, lid = tid & 31;
    float c[16][4] = {};
    float* sA = sm;
    float* sB = sm + 64 * TST;
    float* stage = sm;
    const float* A = (mode == 0 ? doc + (size_t)b * CC * DD
                                : g_dd2q + (size_t)b * CC * DD) + (size_t)m0 * DD;
    const float* Bm = g_s2 + (size_t)b * QQ * DD;
    run_gemm<64>(A, DD, Bm, DD, DD / 32, sA, sB, c, tid);
    frags_to_stage<64>(stage, c, tid, nullptr, nullptr);

    const float* qrb = query + (size_t)b * CC * QQ;
    const size_t qbase = QOFF + (size_t)b * 4 * CC * QQ;
    for (int r = wid; r < 64; r += 8) {
        const size_t roff = (size_t)(m0 + r) * QQ + lid * 4;
        float4 v = *(float4*)&stage[r * STG + lid * 4];
        float4 qv = *(const float4*)(qrb + roff);
        float4 p = make_float4(qv.x * v.x, qv.y * v.y, qv.z * v.z, qv.w * v.w);
        if (mode == 0) {
            *(float4*)(out + qbase + roff) = qv;
            *(float4*)(out + qbase + (size_t)CC * QQ + roff) = v;
            *(float4*)(out + qbase + (size_t)2 * CC * QQ + roff) = p;
            *(float4*)(g_qq2d + (size_t)b * CC * QQ + roff) = v;
        } else {
            *(float4*)(out + qbase + (size_t)3 * CC * QQ + roff) = p;
        }
    }
}

// ============================================================================
extern "C" void kernel_launch(void* const* d_in, const int* in_sizes, int n_in,
                              void* d_out, int out_size) {
    const float* doc = nullptr;
    const float* query = nullptr;
    const float* W = nullptr;
    for (int i = 0; i < n_in; ++i) {
        if      (in_sizes[i] == BB * CC * DD) doc   = (const float*)d_in[i];
        else if (in_sizes[i] == BB * CC * QQ) query = (const float*)d_in[i];
        else if (in_sizes[i] == 3 * CC)       W     = (const float*)d_in[i];
    }
    float* out = (float*)d_out;

    const int DSM128 = 128 * STG * 4;        // 67584 B (stage dominates tiles)
    const int DSM64  = 64 * STG * 4;         // 33792 B
    cudaFuncSetAttribute(k_mma_sim, cudaFuncAttributeMaxDynamicSharedMemorySize, DSM128);
    cudaFuncSetAttribute(k_mma_nn,  cudaFuncAttributeMaxDynamicSharedMemorySize, DSM128);
    cudaFuncSetAttribute(k_mma_nt,  cudaFuncAttributeMaxDynamicSharedMemorySize, DSM64);

    k_t_q  <<<dim3(QQ / 32, CC / 32, BB), dim3(32, 8)>>>(query);
    k_t_d  <<<dim3(DD / 32, CC / 32, BB), dim3(32, 8)>>>(doc, W);
    k_bias <<<BB, 256>>>(doc, query, W);
    k_mma_sim<<<dim3(DD / 128, BB), 256, DSM128>>>();
    k_s2k  <<<BB * QQ, 256>>>();
    k_mma_nn<<<dim3(DD / 128, CC / 128, BB), 256, DSM128>>>(query, doc, out, 0);
    k_mma_nt<<<dim3(CC / 64, BB), 256, DSM64>>>(doc, query, out, 0);
    k_mma_nn<<<dim3(DD / 128, CC / 128, BB), 256, DSM128>>>(query, doc, out, 1);
    k_mma_nt<<<dim3(CC / 64, BB), 256, DSM64>>>(doc, query, out, 1);
}

// round 5
// speedup vs baseline: 1.4842x; 1.2277x over previous
#include <cuda_runtime.h>
#include <cstdint>
#include <math.h>

#define BB 32
#define CC 256
#define DD 1024
#define QQ 128

#define QOFF ((size_t)BB * 4 * CC * DD)   // q_output offset in floats
#define STG 132                            // stage stride (floats)
#define TST 36                             // mma tile stride (floats)

// ---------------- scratch (device globals) ----------------------------------
__device__ float g_sim [BB * QQ * DD];   // sim with biases          16 MB
__device__ float g_s1t [BB * DD * QQ];   // softmax over q, transposed [d][q]
__device__ float g_s2  [BB * QQ * DD];   // softmax over d           16 MB
__device__ float g_dd2q[BB * CC * DD];   // d_d2q                    32 MB
__device__ float g_qq2d[BB * CC * QQ];   // q_q2d                     4 MB
__device__ float g_qT  [BB * QQ * CC];   // query^T [q][c]            4 MB
__device__ float g_dT  [BB * DD * CC];   // (w_s*doc)^T [d][c]       32 MB
__device__ float g_aq  [BB * QQ];
__device__ float g_ad  [BB * DD];

// ---------------- helpers ----------------------------------------------------
__device__ __forceinline__ uint32_t smem_u32(const void* p) {
    uint32_t a;
    asm("{ .reg .u64 t; cvta.to.shared.u64 t, %1; cvt.u32.u64 %0, t; }"
        : "=r"(a) : "l"(p));
    return a;
}
__device__ __forceinline__ void cp_async16(uint32_t dst, const void* src) {
    asm volatile("cp.async.cg.shared.global [%0], [%1], 16;"
                 :: "r"(dst), "l"(src));
}
#define CP_COMMIT() asm volatile("cp.async.commit_group;" ::: "memory")
#define CP_WAIT0()  asm volatile("cp.async.wait_group 0;" ::: "memory")

__device__ __forceinline__ void mma_tf32(float c[4], const uint32_t a[4],
                                         const uint32_t b[2]) {
    asm volatile(
        "mma.sync.aligned.m16n8k8.row.col.f32.tf32.tf32.f32 "
        "{%0,%1,%2,%3}, {%4,%5,%6,%7}, {%8,%9}, {%0,%1,%2,%3};\n"
        : "+f"(c[0]), "+f"(c[1]), "+f"(c[2]), "+f"(c[3])
        : "r"(a[0]), "r"(a[1]), "r"(a[2]), "r"(a[3]), "r"(b[0]), "r"(b[1]));
}

// Issue cp.async for a ROWS x 32 fp32 tile (K-major, ld=ldk) -> smem stride TST.
template<int ROWS>
__device__ __forceinline__ void tile_cp(uint32_t dst, const float* src,
                                        int ldk, int k0, int tid) {
    #pragma unroll
    for (int i = 0; i < ROWS / 32; ++i) {
        int idx = i * 256 + tid;
        int row = idx >> 3, cb = (idx & 7) * 4;
        cp_async16(dst + (uint32_t)(row * TST + cb) * 4,
                   src + (size_t)row * ldk + k0 + cb);
    }
}

// GEMM core, 2-stage cp.async pipeline.
// C[MTILE x 128] = A[MTILE x K] * B[128 x K]^T, both K-major fp32 (tf32-truncated).
// MTILE=128 -> warps 4x2 (NJ=8); MTILE=64 -> warps 2x4 (NJ=4).
template<int MTILE>
__device__ __forceinline__ void run_gemm(const float* A, int lda,
                                         const float* Bm, int ldb, int kIters,
                                         float* sm, float (*c)[4], int tid) {
    const int wid = tid >> 5, lane = tid & 31;
    const int NJ = (MTILE == 128) ? 8 : 4;
    const int wm = (MTILE == 128) ? (wid & 3) * 32 : (wid & 1) * 32;
    const int wn = (MTILE == 128) ? (wid >> 2) * 64 : (wid >> 1) * 32;
    const int g = lane >> 2, tg = lane & 3;
    const int AT = MTILE * TST;
    const int STAGE = AT + 128 * TST;
    const uint32_t sm_u = smem_u32(sm);

    // prologue: stage 0
    tile_cp<MTILE>(sm_u, A, lda, 0, tid);
    tile_cp<128>(sm_u + AT * 4, Bm, ldb, 0, tid);
    CP_COMMIT();

    for (int it = 0; it < kIters; ++it) {
        CP_WAIT0();
        __syncthreads();                 // stage it%2 visible; prev mma done
        const int s = it & 1;
        if (it + 1 < kIters) {           // prefetch next stage (overlaps mma)
            const int ns = 1 - s;
            tile_cp<MTILE>(sm_u + (uint32_t)(ns * STAGE) * 4, A, lda,
                           (it + 1) * 32, tid);
            tile_cp<128>(sm_u + (uint32_t)(ns * STAGE + AT) * 4, Bm, ldb,
                         (it + 1) * 32, tid);
            CP_COMMIT();
        }
        const float* sA = sm + s * STAGE;
        const float* sB = sA + AT;
        #pragma unroll
        for (int ks = 0; ks < 4; ++ks) {
            const int kb = ks * 8;
            uint32_t a[2][4], b[8][2];
            #pragma unroll
            for (int i = 0; i < 2; ++i) {
                const float* p = sA + (wm + i * 16 + g) * TST + kb + tg;
                a[i][0] = __float_as_uint(p[0]);
                a[i][1] = __float_as_uint(p[8 * TST]);
                a[i][2] = __float_as_uint(p[4]);
                a[i][3] = __float_as_uint(p[8 * TST + 4]);
            }
            #pragma unroll
            for (int j = 0; j < NJ; ++j) {
                const float* p = sB + (wn + j * 8 + g) * TST + kb + tg;
                b[j][0] = __float_as_uint(p[0]);
                b[j][1] = __float_as_uint(p[4]);
            }
            #pragma unroll
            for (int i = 0; i < 2; ++i)
                #pragma unroll
                for (int j = 0; j < NJ; ++j)
                    mma_tf32(c[i * 8 + j], a[i], b[j]);
        }
    }
}

// Fragments -> stage smem (stride STG), optional row/col bias.
template<int MTILE>
__device__ __forceinline__ void frags_to_stage(float* stage, float (*c)[4],
                                               int tid, const float* br,
                                               const float* bc) {
    const int wid = tid >> 5, lane = tid & 31;
    const int NJ = (MTILE == 128) ? 8 : 4;
    const int wm = (MTILE == 128) ? (wid & 3) * 32 : (wid & 1) * 32;
    const int wn = (MTILE == 128) ? (wid >> 2) * 64 : (wid >> 1) * 32;
    const int g = lane >> 2, tg = lane & 3;
    __syncthreads();                 // tiles fully consumed (stage aliases them)
    #pragma unroll
    for (int i = 0; i < 2; ++i) {
        const int r0 = wm + i * 16 + g, r1 = r0 + 8;
        const float a0 = br ? br[r0] : 0.f, a1 = br ? br[r1] : 0.f;
        #pragma unroll
        for (int j = 0; j < NJ; ++j) {
            const int col = wn + j * 8 + 2 * tg;
            const float b0 = bc ? bc[col] : 0.f, b1 = bc ? bc[col + 1] : 0.f;
            float* f = c[i * 8 + j];
            stage[r0 * STG + col]     = f[0] + a0 + b0;
            stage[r0 * STG + col + 1] = f[1] + a0 + b1;
            stage[r1 * STG + col]     = f[2] + a1 + b0;
            stage[r1 * STG + col + 1] = f[3] + a1 + b1;
        }
    }
    __syncthreads();
}

// ============================================================================
// Transposes + bias GEMVs
// ============================================================================
__global__ void k_t_q(const float* __restrict__ query) {
    __shared__ float tile[32][33];
    const int b = blockIdx.z, q0 = blockIdx.x * 32, c0 = blockIdx.y * 32;
    const int tx = threadIdx.x, ty = threadIdx.y;
    const float* src = query + (size_t)b * CC * QQ;
    float* dst = g_qT + (size_t)b * QQ * CC;
    #pragma unroll
    for (int r = ty; r < 32; r += 8)
        tile[r][tx] = src[(size_t)(c0 + r) * QQ + q0 + tx];
    __syncthreads();
    #pragma unroll
    for (int r = ty; r < 32; r += 8)
        dst[(size_t)(q0 + r) * CC + c0 + tx] = tile[tx][r];
}
__global__ void k_t_d(const float* __restrict__ doc, const float* __restrict__ W) {
    __shared__ float tile[32][33];
    const int b = blockIdx.z, d0 = blockIdx.x * 32, c0 = blockIdx.y * 32;
    const int tx = threadIdx.x, ty = threadIdx.y;
    const float* src = doc + (size_t)b * CC * DD;
    float* dst = g_dT + (size_t)b * DD * CC;
    #pragma unroll
    for (int r = ty; r < 32; r += 8)
        tile[r][tx] = src[(size_t)(c0 + r) * DD + d0 + tx];
    __syncthreads();
    const float ws = W[2 * CC + c0 + tx];
    #pragma unroll
    for (int r = ty; r < 32; r += 8)
        dst[(size_t)(d0 + r) * CC + c0 + tx] = tile[tx][r] * ws;
}
__global__ void __launch_bounds__(256) k_bias(const float* __restrict__ doc,
                                              const float* __restrict__ query,
                                              const float* __restrict__ W) {
    const int b = blockIdx.x, tid = threadIdx.x;
    const float* qb = query + (size_t)b * CC * QQ;
    const float* db = doc + (size_t)b * CC * DD;
    if (tid < QQ) {
        float s = 0.f;
        #pragma unroll 4
        for (int c = 0; c < CC; ++c) s = fmaf(W[CC + c], qb[c * QQ + tid], s);
        g_aq[b * QQ + tid] = s;
    }
    for (int d = tid; d < DD; d += 256) {
        float s = 0.f;
        #pragma unroll 4
        for (int c = 0; c < CC; ++c) s = fmaf(W[c], db[(size_t)c * DD + d], s);
        g_ad[b * DD + d] = s;
    }
}

// ============================================================================
// sim: sim[q,d] = qT[q,:].dT[d,:] + aq + ad  (K=256), write g_sim,
// column softmax over q -> g_s1t[d][q]. Grid (8, B), 256 thr.
// ============================================================================
__global__ void __launch_bounds__(256) k_mma_sim() {
    extern __shared__ float sm[];
    __shared__ float sh_aq[128];
    __shared__ float sh_ad[128];
    const int b = blockIdx.y, n0 = blockIdx.x * 128;
    const int tid = threadIdx.x, wid = tid >> 5, lid = tid & 31;
    if (tid < 128) {
        sh_aq[tid] = g_aq[b * QQ + tid];
        sh_ad[tid] = g_ad[b * DD + n0 + tid];
    }
    float c[16][4] = {};
    float* stage = sm;
    const float* A  = g_qT + (size_t)b * QQ * CC;
    const float* Bm = g_dT + (size_t)b * DD * CC + (size_t)n0 * CC;
    run_gemm<128>(A, CC, Bm, CC, CC / 32, sm, c, tid);
    frags_to_stage<128>(stage, c, tid, sh_aq, sh_ad);

    float* simb = g_sim + (size_t)b * QQ * DD;
    for (int r = wid; r < 128; r += 8)
        *(float4*)(simb + (size_t)r * DD + n0 + lid * 4) =
            *(float4*)&stage[r * STG + lid * 4];
    __syncthreads();

    if (tid < 128) {
        float m = -1e30f;
        #pragma unroll 4
        for (int q = 0; q < 128; ++q) m = fmaxf(m, stage[q * STG + tid]);
        float s = 0.f;
        #pragma unroll 4
        for (int q = 0; q < 128; ++q) {
            float e = __expf(stage[q * STG + tid] - m);
            stage[q * STG + tid] = e;
            s += e;
        }
        const float inv = 1.f / s;
        float* dst = g_s1t + ((size_t)b * DD + n0 + tid) * QQ;
        #pragma unroll 4
        for (int q = 0; q < 128; q += 4)
            *(float4*)(dst + q) = make_float4(stage[(q + 0) * STG + tid] * inv,
                                              stage[(q + 1) * STG + tid] * inv,
                                              stage[(q + 2) * STG + tid] * inv,
                                              stage[(q + 3) * STG + tid] * inv);
    }
}

// ============================================================================
// s2: row softmax of g_sim over d. Grid B*Q, 256 threads.
// ============================================================================
__global__ void __launch_bounds__(256) k_s2k() {
    const size_t row = blockIdx.x;
    const float4* src = (const float4*)(g_sim + row * DD);
    float4* dst = (float4*)(g_s2 + row * DD);
    const int tid = threadIdx.x;
    __shared__ float sred[8];
    __shared__ float sbc;
    float4 v = src[tid];
    float m = fmaxf(fmaxf(v.x, v.y), fmaxf(v.z, v.w));
    #pragma unroll
    for (int o = 16; o > 0; o >>= 1) m = fmaxf(m, __shfl_xor_sync(0xffffffffu, m, o));
    if ((tid & 31) == 0) sred[tid >> 5] = m;
    __syncthreads();
    if (tid == 0) {
        float t = sred[0];
        #pragma unroll
        for (int i = 1; i < 8; ++i) t = fmaxf(t, sred[i]);
        sbc = t;
    }
    __syncthreads();
    const float M = sbc;
    float4 e;
    e.x = __expf(v.x - M); e.y = __expf(v.y - M);
    e.z = __expf(v.z - M); e.w = __expf(v.w - M);
    float s = e.x + e.y + e.z + e.w;
    #pragma unroll
    for (int o = 16; o > 0; o >>= 1) s += __shfl_xor_sync(0xffffffffu, s, o);
    __syncthreads();
    if ((tid & 31) == 0) sred[tid >> 5] = s;
    __syncthreads();
    if (tid == 0) {
        float t = 0.f;
        #pragma unroll
        for (int i = 0; i < 8; ++i) t += sred[i];
        sbc = 1.f / t;
    }
    __syncthreads();
    const float r = sbc;
    dst[tid] = make_float4(e.x * r, e.y * r, e.z * r, e.w * r);
}

// ============================================================================
// NN: out[c,d] = A[c,:q] . s1t[d,:q]  (K=128). Grid (8, 2, B).
//   mode 0: A=query  -> ch0 doc, ch1 d_d2q, ch2 doc*d_d2q, + g_dd2q
//   mode 1: A=g_qq2d -> ch3 doc*d_q2d
// ============================================================================
__global__ void __launch_bounds__(256) k_mma_nn(const float* __restrict__ query,
                                                const float* __restrict__ doc,
                                                float* __restrict__ out, int mode) {
    extern __shared__ float sm[];
    const int b = blockIdx.z, m0 = blockIdx.y * 128, n0 = blockIdx.x * 128;
    const int tid = threadIdx.x, wid = tid >> 5, lid = tid & 31;
    float c[16][4] = {};
    float* stage = sm;
    const float* A = (mode == 0 ? query + (size_t)b * CC * QQ
                                : g_qq2d + (size_t)b * CC * QQ) + (size_t)m0 * QQ;
    const float* Bm = g_s1t + (size_t)b * DD * QQ + (size_t)n0 * QQ;
    run_gemm<128>(A, QQ, Bm, QQ, QQ / 32, sm, c, tid);
    frags_to_stage<128>(stage, c, tid, nullptr, nullptr);

    const float* docb = doc + (size_t)b * CC * DD;
    const size_t dbase = (size_t)b * 4 * CC * DD;
    for (int r = wid; r < 128; r += 8) {
        const size_t roff = (size_t)(m0 + r) * DD + n0 + lid * 4;
        float4 v = *(float4*)&stage[r * STG + lid * 4];
        float4 dv = *(const float4*)(docb + roff);
        float4 p = make_float4(dv.x * v.x, dv.y * v.y, dv.z * v.z, dv.w * v.w);
        if (mode == 0) {
            *(float4*)(out + dbase + roff) = dv;
            *(float4*)(out + dbase + (size_t)CC * DD + roff) = v;
            *(float4*)(out + dbase + (size_t)2 * CC * DD + roff) = p;
            *(float4*)(g_dd2q + (size_t)b * CC * DD + roff) = v;
        } else {
            *(float4*)(out + dbase + (size_t)3 * CC * DD + roff) = p;
        }
    }
}

// ============================================================================
// NT: out[c,q] = A[c,:d] . s2[q,:d]  (K=1024). MTILE=64, grid (4, B).
//   mode 0: A=doc    -> ch0 query, ch1 q_q2d, ch2 query*q_q2d, + g_qq2d
//   mode 1: A=g_dd2q -> ch3 query*q_d2q
// ============================================================================
__global__ void __launch_bounds__(256) k_mma_nt(const float* __restrict__ doc,
                                                const float* __restrict__ query,
                                                float* __restrict__ out, int mode) {
    extern __shared__ float sm[];
    const int b = blockIdx.y, m0 = blockIdx.x * 64;
    const int tid = threadIdx.x, wid = tid >> 5, lid = tid & 31;
    float c[16][4] = {};
    float* stage = sm;
    const float* A = (mode == 0 ? doc + (size_t)b * CC * DD
                                : g_dd2q + (size_t)b * CC * DD) + (size_t)m0 * DD;
    const float* Bm = g_s2 + (size_t)b * QQ * DD;
    run_gemm<64>(A, DD, Bm, DD, DD / 32, sm, c, tid);
    frags_to_stage<64>(stage, c, tid, nullptr, nullptr);

    const float* qrb = query + (size_t)b * CC * QQ;
    const size_t qbase = QOFF + (size_t)b * 4 * CC * QQ;
    for (int r = wid; r < 64; r += 8) {
        const size_t roff = (size_t)(m0 + r) * QQ + lid * 4;
        float4 v = *(float4*)&stage[r * STG + lid * 4];
        float4 qv = *(const float4*)(qrb + roff);
        float4 p = make_float4(qv.x * v.x, qv.y * v.y, qv.z * v.z, qv.w * v.w);
        if (mode == 0) {
            *(float4*)(out + qbase + roff) = qv;
            *(float4*)(out + qbase + (size_t)CC * QQ + roff) = v;
            *(float4*)(out + qbase + (size_t)2 * CC * QQ + roff) = p;
            *(float4*)(g_qq2d + (size_t)b * CC * QQ + roff) = v;
        } else {
            *(float4*)(out + qbase + (size_t)3 * CC * QQ + roff) = p;
        }
    }
}

// ============================================================================
extern "C" void kernel_launch(void* const* d_in, const int* in_sizes, int n_in,
                              void* d_out, int out_size) {
    const float* doc = nullptr;
    const float* query = nullptr;
    const float* W = nullptr;
    for (int i = 0; i < n_in; ++i) {
        if      (in_sizes[i] == BB * CC * DD) doc   = (const float*)d_in[i];
        else if (in_sizes[i] == BB * CC * QQ) query = (const float*)d_in[i];
        else if (in_sizes[i] == 3 * CC)       W     = (const float*)d_in[i];
    }
    float* out = (float*)d_out;

    // 2 pipeline stages of (A+B) tiles; stage buffer aliases them afterwards.
    const int DSM128 = 2 * (128 + 128) * TST * 4;   // 73728 B
    const int DSM64  = 2 * (64 + 128) * TST * 4;    // 55296 B
    cudaFuncSetAttribute(k_mma_sim, cudaFuncAttributeMaxDynamicSharedMemorySize, DSM128);
    cudaFuncSetAttribute(k_mma_nn,  cudaFuncAttributeMaxDynamicSharedMemorySize, DSM128);
    cudaFuncSetAttribute(k_mma_nt,  cudaFuncAttributeMaxDynamicSharedMemorySize, DSM64);

    k_t_q  <<<dim3(QQ / 32, CC / 32, BB), dim3(32, 8)>>>(query);
    k_t_d  <<<dim3(DD / 32, CC / 32, BB), dim3(32, 8)>>>(doc, W);
    k_bias <<<BB, 256>>>(doc, query, W);
    k_mma_sim<<<dim3(DD / 128, BB), 256, DSM128>>>();
    k_s2k  <<<BB * QQ, 256>>>();
    k_mma_nn<<<dim3(DD / 128, CC / 128, BB), 256, DSM128>>>(query, doc, out, 0);
    k_mma_nt<<<dim3(CC / 64, BB), 256, DSM64>>>(doc, query, out, 0);
    k_mma_nn<<<dim3(DD / 128, CC / 128, BB), 256, DSM128>>>(query, doc, out, 1);
    k_mma_nt<<<dim3(CC / 64, BB), 256, DSM64>>>(doc, query, out, 1);
}